// round 15
// baseline (speedup 1.0000x reference)
#include <cuda_runtime.h>
#include <cuda_fp16.h>
#include <cstdint>

// Fused sudoku-GNN, split-fp16 HMMA, warp-specialized two-set pipeline.
// 384 threads: warps 0-7 = T (MMA + epilogue), warps 8-11 = V (A-op + W cp.async).
// R15 = R12 skeleton (validated barrier protocol: one arriver + one syncer
// per barrier id) + raw-accumulator epilogue: layers 0-4 T stores bare acc;
// V's aop fuses relu(x + bias_f) into its tally-load pass. Layer 5 epi
// applies bias+relu and splits to hi/lo for the output MMA.
// Barriers: id1 X+W ready (V arrive/T sync, 384), id2 X free (T arrive/V sync,
// 384), id3 Y ready (384), id4 Y free (384), id5 W free (T arrive/V sync,
// 384), id6 T-only epi guard (256).

#define ASTB 400         // A row bytes (25*16 -> conflict-free)
#define WSTB 272         // W row bytes (17*16)

#define SM_AX    0            // 128*400 = 51200
#define SM_AY    51200
#define SM_WHI0  102400       // 34816
#define SM_WHI1  137216
#define SM_WLO   172032
#define SM_BIAS  206848       // 2*512 ping/pong
#define SM_STAGE 207872       // Win staging (5120) / logits (5832)
#define SM_XS    213760       // 162 ints
#define SMEM_BYTES 214432

__device__ __align__(16) unsigned char g_Wh[6][34816];
__device__ __align__(16) unsigned char g_Wl[6][34816];
__device__ __align__(16) unsigned char g_WoH[4352];   // WoutT padded [16][136]
__device__ __align__(16) unsigned char g_WoL[4352];

__device__ __forceinline__ uint32_t smem_u32(const void* p) {
    uint32_t a;
    asm("{ .reg .u64 t; cvta.to.shared.u64 t, %1; cvt.u32.u64 %0, t; }" : "=r"(a) : "l"(p));
    return a;
}
#define CPA16(dst, src) asm volatile("cp.async.cg.shared.global [%0], [%1], 16;" :: "r"(dst), "l"(src))
#define CPA_COMMIT()    asm volatile("cp.async.commit_group;" ::: "memory")
#define CPA_WAIT0()     asm volatile("cp.async.wait_group 0;" ::: "memory")
#define BSYNC(id, cnt)  asm volatile("bar.sync %0, %1;" :: "r"(id), "r"(cnt) : "memory")
#define BARRIVE(id, cnt) asm volatile("bar.arrive %0, %1;" :: "r"(id), "r"(cnt) : "memory")

#define LDMX4(r, addr)                                                        \
    asm volatile("ldmatrix.sync.aligned.m8n8.x4.shared.b16 {%0,%1,%2,%3}, [%4];" \
        : "=r"((r)[0]), "=r"((r)[1]), "=r"((r)[2]), "=r"((r)[3]) : "r"(addr))
#define LDMX4T(r, addr)                                                       \
    asm volatile("ldmatrix.sync.aligned.m8n8.x4.trans.shared.b16 {%0,%1,%2,%3}, [%4];" \
        : "=r"((r)[0]), "=r"((r)[1]), "=r"((r)[2]), "=r"((r)[3]) : "r"(addr))
#define MMA16816(d, a, b)                                                     \
    asm volatile("mma.sync.aligned.m16n8k16.row.col.f32.f16.f16.f32 "         \
        "{%0,%1,%2,%3},{%4,%5,%6,%7},{%8,%9},{%0,%1,%2,%3};"                  \
        : "+f"((d)[0]), "+f"((d)[1]), "+f"((d)[2]), "+f"((d)[3])              \
        : "r"((a)[0]), "r"((a)[1]), "r"((a)[2]), "r"((a)[3]),                 \
          "r"((b)[0]), "r"((b)[1]))

// ---------- prep: split W to fp16 hi/lo [n][k] ----------
__global__ void prep_kernel(const float* __restrict__ Wlay,
                            const float* __restrict__ Wout) {
    int t = blockIdx.x * blockDim.x + threadIdx.x;
    if (t < 6 * 128 * 128) {
        int l = t >> 14, r = t & 16383, k = r >> 7, n = r & 127;
        float w = Wlay[t];
        __half hi = __float2half_rn(w);
        __half lo = __float2half_rn(w - __half2float(hi));
        uint32_t off = (uint32_t)n * WSTB + (uint32_t)k * 2;
        *(__half*)(g_Wh[l] + off) = hi;
        *(__half*)(g_Wl[l] + off) = lo;
    } else if (t < 6 * 128 * 128 + 16 * 128) {
        int r = t - 6 * 128 * 128;
        int j = r >> 7, k = r & 127;
        float w = (j < 9) ? Wout[k * 9 + j] : 0.f;
        __half hi = __float2half_rn(w);
        __half lo = __float2half_rn(w - __half2float(hi));
        uint32_t off = (uint32_t)j * WSTB + (uint32_t)k * 2;
        *(__half*)(g_WoH + off) = hi;
        *(__half*)(g_WoL + off) = lo;
    }
}

// ---------- A-op on one row: relu(raw+bk) tallies -> hi/lo in place ----------
__device__ __forceinline__ void aop_row(unsigned char* __restrict__ rowp, float bk) {
    const uint4* cp = (const uint4*)rowp;
    float Trow[9][3], Tcol[3][9];
#pragma unroll
    for (int i = 0; i < 9; i++) { Trow[i][0] = Trow[i][1] = Trow[i][2] = 0.f; }
#pragma unroll
    for (int j = 0; j < 9; j++) { Tcol[0][j] = Tcol[1][j] = Tcol[2][j] = 0.f; }
#pragma unroll
    for (int c = 0; c < 20; c++) {
        uint4 u = cp[c];
        float vv[4] = {fmaxf(__uint_as_float(u.x) + bk, 0.f),
                       fmaxf(__uint_as_float(u.y) + bk, 0.f),
                       fmaxf(__uint_as_float(u.z) + bk, 0.f),
                       fmaxf(__uint_as_float(u.w) + bk, 0.f)};
#pragma unroll
        for (int e = 0; e < 4; e++) {
            const int n = 4 * c + e, i = n / 9, j = n - 9 * i;
            Trow[i][j / 3] += vv[e];
            Tcol[i / 3][j] += vv[e];
        }
    }
    const float v80 = fmaxf(((const float*)rowp)[80] + bk, 0.f);
    Trow[8][2] += v80; Tcol[2][8] += v80;

    float RS[9], CS[9], BS[3][3];
#pragma unroll
    for (int i = 0; i < 9; i++) RS[i] = Trow[i][0] + Trow[i][1] + Trow[i][2];
#pragma unroll
    for (int j = 0; j < 9; j++) CS[j] = Tcol[0][j] + Tcol[1][j] + Tcol[2][j];
#pragma unroll
    for (int bi = 0; bi < 3; bi++)
#pragma unroll
        for (int bj = 0; bj < 3; bj++)
            BS[bi][bj] = Trow[3 * bi][bj] + Trow[3 * bi + 1][bj] + Trow[3 * bi + 2][bj];
    const float inv21 = 1.0f / 21.0f;
    float PR[9][3], CC[3][9];
#pragma unroll
    for (int i = 0; i < 9; i++)
#pragma unroll
        for (int jb = 0; jb < 3; jb++)
            PR[i][jb] = (RS[i] + BS[i / 3][jb] - Trow[i][jb]) * inv21;
#pragma unroll
    for (int ib = 0; ib < 3; ib++)
#pragma unroll
        for (int j = 0; j < 9; j++)
            CC[ib][j] = (CS[j] - Tcol[ib][j]) * inv21;

    unsigned char* hip = rowp;
    unsigned char* lop = rowp + 192;
#pragma unroll
    for (int c = 0; c < 10; c++) {
        uint32_t oh[4], ol[4];
#pragma unroll
        for (int e = 0; e < 4; e++) {
            const int n = 8 * c + 2 * e;
            const int i0 = n / 9, j0 = n - 9 * i0;
            const int n1 = n + 1, i1 = n1 / 9, j1 = n1 - 9 * i1;
            float g0 = PR[i0][j0 / 3] + CC[i0 / 3][j0];
            float g1 = PR[i1][j1 / 3] + CC[i1 / 3][j1];
            __half2 hh2 = __floats2half2_rn(g0, g1);
            float2 hf = __half22float2(hh2);
            __half2 ll2 = __floats2half2_rn(g0 - hf.x, g1 - hf.y);
            oh[e] = *(uint32_t*)&hh2;
            ol[e] = *(uint32_t*)&ll2;
        }
        *(uint4*)(hip + 16 * c) = make_uint4(oh[0], oh[1], oh[2], oh[3]);
        *(uint4*)(lop + 16 * c) = make_uint4(ol[0], ol[1], ol[2], ol[3]);
    }
    {
        float gg = PR[8][2] + CC[2][8];
        __half hh = __float2half_rn(gg);
        *(__half*)(hip + 160) = hh;
        *(__half*)(lop + 160) = __float2half_rn(gg - __half2float(hh));
    }
}

__global__ void __launch_bounds__(384)
gnn_mma(const long long* __restrict__ xraw,
        const float* __restrict__ Win,  const float* __restrict__ bin,
        const float* __restrict__ blay, const float* __restrict__ bout,
        float* __restrict__ out) {
    extern __shared__ unsigned char smem[];
    const int t = threadIdx.x, wid = t >> 5, lane = t & 31;
    const uint32_t sbase = smem_u32(smem);

    // ---- prologue: cp.async W(0) + bias(0) ----
    for (int i = t * 16; i < 34816; i += 384 * 16) {
        CPA16(sbase + SM_WHI0 + i, g_Wh[0] + i);
        CPA16(sbase + SM_WLO + i, g_Wl[0] + i);
    }
    if (t < 32) CPA16(sbase + SM_BIAS + t * 16, (const unsigned char*)blay + t * 16);
    CPA_COMMIT();

    // ---- x load (int64 vs int32 robust) + Win ----
    long long probe = (t < 162) ? xraw[t] : 0;
    const int is32 = __syncthreads_or(probe > 9 || probe < 0);
    {
        const long long gbase = (long long)blockIdx.x * 162;
        for (int i = t; i < 162; i += 384)
            ((int*)(smem + SM_XS))[i] =
                is32 ? ((const int*)xraw)[gbase + i] : (int)xraw[gbase + i];
    }
    for (int i = t; i < 1280; i += 384)
        ((float*)(smem + SM_STAGE))[i] = Win[i];
    __syncthreads();

    // ---- h0 raw + aop(layer 0) with fused bin+relu ----
    if (t < 256) {
        const int f = t & 127, s = t >> 7;
        unsigned char* rowp = smem + (s ? SM_AY : SM_AX) + f * ASTB;
        const float* Wi = (const float*)(smem + SM_STAGE);
        const int* xr = (const int*)(smem + SM_XS) + s * 81;
#pragma unroll 5
        for (int c = 0; c < 20; c++) {
            float4 o;
            o.x = Wi[xr[4 * c + 0] * 128 + f];
            o.y = Wi[xr[4 * c + 1] * 128 + f];
            o.z = Wi[xr[4 * c + 2] * 128 + f];
            o.w = Wi[xr[4 * c + 3] * 128 + f];
            *(float4*)(rowp + 16 * c) = o;
        }
        ((float*)rowp)[80] = Wi[xr[80] * 128 + f];
        aop_row(rowp, bin[f]);
    }
    CPA_WAIT0();
    __syncthreads();

    const uint32_t rowSel = (uint32_t)((lane & 7) + ((lane >> 4) << 3));
    const uint32_t aFrag  = rowSel * ASTB + ((lane >> 3) & 1) * 16;
    const uint32_t bPairOff = rowSel * WSTB + ((lane >> 3) & 1) * 16;

    if (wid < 8) {
        // ================= TENSOR GROUP =================
        const int mg = wid & 1, ng = wid >> 1;
        const int m0 = mg * 48, n0e = ng * 32;
        const uint32_t n0W = (uint32_t)n0e * WSTB;
#pragma unroll 1
        for (int l = 0; l <= 6; l++) {
            const uint32_t whiB = (l & 1) ? SM_WHI1 : SM_WHI0;
#pragma unroll 1
            for (int s2 = 0; s2 < 2; s2++) {
                BSYNC(s2 ? 3 : 1, 384);
                const uint32_t abase = s2 ? SM_AY : SM_AX;
                if (l < 6) {
                    float acc[3][4][4];
#pragma unroll
                    for (int ti = 0; ti < 3; ti++)
#pragma unroll
                        for (int tj = 0; tj < 4; tj++)
#pragma unroll
                            for (int e = 0; e < 4; e++) acc[ti][tj][e] = 0.f;
                    const uint32_t aHi = sbase + abase + aFrag + (uint32_t)m0 * 2;
                    const uint32_t aLo = aHi + 192;
                    const uint32_t bLo = sbase + SM_WLO + n0W + bPairOff;
                    const uint32_t bHi = sbase + whiB + n0W + bPairOff;
                    // ---- fused 3-term k-loop ----
#pragma unroll
                    for (int ks = 0; ks < 8; ks++) {
                        uint32_t bh[4][2], bl[4][2], r4[4];
                        LDMX4(r4, bHi + ks * 32);
                        bh[0][0] = r4[0]; bh[0][1] = r4[1]; bh[1][0] = r4[2]; bh[1][1] = r4[3];
                        LDMX4(r4, bHi + 16 * WSTB + ks * 32);
                        bh[2][0] = r4[0]; bh[2][1] = r4[1]; bh[3][0] = r4[2]; bh[3][1] = r4[3];
                        LDMX4(r4, bLo + ks * 32);
                        bl[0][0] = r4[0]; bl[0][1] = r4[1]; bl[1][0] = r4[2]; bl[1][1] = r4[3];
                        LDMX4(r4, bLo + 16 * WSTB + ks * 32);
                        bl[2][0] = r4[0]; bl[2][1] = r4[1]; bl[3][0] = r4[2]; bl[3][1] = r4[3];
#pragma unroll
                        for (int ti = 0; ti < 3; ti++) {
                            uint32_t ah[4], al[4];
                            LDMX4T(ah, aHi + ks * 6400 + ti * 32);
                            LDMX4T(al, aLo + ks * 6400 + ti * 32);
#pragma unroll
                            for (int tj = 0; tj < 4; tj++) MMA16816(acc[ti][tj], ah, bh[tj]);
#pragma unroll
                            for (int tj = 0; tj < 4; tj++) MMA16816(acc[ti][tj], ah, bl[tj]);
#pragma unroll
                            for (int tj = 0; tj < 4; tj++) MMA16816(acc[ti][tj], al, bh[tj]);
                        }
                    }
                    if (s2) BARRIVE(5, 384);          // W(l) reads done
                    BSYNC(6, 256);                    // T-only: A reads done before epi writes
                    if (l < 5) {
                        // raw accumulator stores (bias+relu fused into V's aop)
#pragma unroll
                        for (int ti = 0; ti < 3; ti++) {
                            const int rb = m0 + 16 * ti + (lane >> 2);
#pragma unroll
                            for (int tj = 0; tj < 4; tj++) {
                                const int c0 = n0e + 8 * tj + 2 * (lane & 3);
#pragma unroll
                                for (int hh = 0; hh < 2; hh++) {
                                    const int r = rb + 8 * hh;
                                    if (r < 81) {
                                        *(float*)(smem + abase + (uint32_t)c0 * ASTB + r * 4) =
                                            acc[ti][tj][2 * hh];
                                        *(float*)(smem + abase + (uint32_t)(c0 + 1) * ASTB + r * 4) =
                                            acc[ti][tj][2 * hh + 1];
                                    }
                                }
                            }
                        }
                    } else {
                        // layer 5: bias+relu, split directly to hi/lo
                        const float* bias = (const float*)(smem + SM_BIAS + (l & 1) * 512);
#pragma unroll
                        for (int ti = 0; ti < 3; ti++) {
                            const int rb = m0 + 16 * ti + (lane >> 2);
#pragma unroll
                            for (int tj = 0; tj < 4; tj++) {
                                const int c0 = n0e + 8 * tj + 2 * (lane & 3);
                                const float bb0 = bias[c0], bb1 = bias[c0 + 1];
#pragma unroll
                                for (int hh = 0; hh < 2; hh++) {
                                    const int r = rb + 8 * hh;
                                    if (r < 81) {
                                        float v0 = fmaxf(acc[ti][tj][2 * hh] + bb0, 0.f);
                                        float v1 = fmaxf(acc[ti][tj][2 * hh + 1] + bb1, 0.f);
                                        __half h0h = __float2half_rn(v0);
                                        __half h1h = __float2half_rn(v1);
                                        const uint32_t o0 = (uint32_t)c0 * ASTB + r * 2;
                                        const uint32_t o1 = (uint32_t)(c0 + 1) * ASTB + r * 2;
                                        *(__half*)(smem + abase + o0) = h0h;
                                        *(__half*)(smem + abase + o1) = h1h;
                                        *(__half*)(smem + abase + 192 + o0) =
                                            __float2half_rn(v0 - __half2float(h0h));
                                        *(__half*)(smem + abase + 192 + o1) =
                                            __float2half_rn(v1 - __half2float(h1h));
                                    }
                                }
                            }
                        }
                    }
                    BARRIVE(s2 ? 4 : 2, 384);         // set free for V's next aop
                } else {
                    // ---- output layer: warps 0-5, 1 m16-tile x 16 n ----
                    if (wid < 6) {
                        float acc2[2][4];
#pragma unroll
                        for (int tj = 0; tj < 2; tj++)
#pragma unroll
                            for (int e = 0; e < 4; e++) acc2[tj][e] = 0.f;
                        const uint32_t aHi = sbase + abase + aFrag + (uint32_t)wid * 32;
                        const uint32_t aLo = aHi + 192;
                        const uint32_t bH = sbase + SM_WHI0 + bPairOff;
                        const uint32_t bL = sbase + SM_WLO + bPairOff;
#pragma unroll
                        for (int ks = 0; ks < 8; ks++) {
                            uint32_t b1[2][2], b2[2][2], r4[4];
                            LDMX4(r4, bH + ks * 32);
                            b1[0][0] = r4[0]; b1[0][1] = r4[1]; b1[1][0] = r4[2]; b1[1][1] = r4[3];
                            LDMX4(r4, bL + ks * 32);
                            b2[0][0] = r4[0]; b2[0][1] = r4[1]; b2[1][0] = r4[2]; b2[1][1] = r4[3];
                            uint32_t ah[4], al[4];
                            LDMX4T(ah, aHi + ks * 6400);
                            LDMX4T(al, aLo + ks * 6400);
#pragma unroll
                            for (int tj = 0; tj < 2; tj++) {
                                MMA16816(acc2[tj], ah, b1[tj]);
                                MMA16816(acc2[tj], ah, b2[tj]);
                                MMA16816(acc2[tj], al, b1[tj]);
                            }
                        }
                        float* stg = (float*)(smem + SM_STAGE);
#pragma unroll
                        for (int tj = 0; tj < 2; tj++) {
                            const int c0 = 8 * tj + 2 * (lane & 3);
#pragma unroll
                            for (int hh = 0; hh < 2; hh++) {
                                const int r = wid * 16 + (lane >> 2) + 8 * hh;
                                if (r < 81) {
                                    if (c0 < 9)
                                        stg[s2 * 729 + r * 9 + c0] = acc2[tj][2 * hh] + bout[c0];
                                    if (c0 + 1 < 9)
                                        stg[s2 * 729 + r * 9 + c0 + 1] = acc2[tj][2 * hh + 1] + bout[c0 + 1];
                                }
                            }
                        }
                    }
                }
            }
        }
    } else {
        // ================= VECTOR GROUP =================
        const int vf = t & 127;
        unsigned char* cX = smem + SM_AX + vf * ASTB;
        unsigned char* cY = smem + SM_AY + vf * ASTB;
        BARRIVE(1, 384);
        BARRIVE(3, 384);
#pragma unroll 1
        for (int l = 0; l < 6; l++) {
            const float* bias = (const float*)(smem + SM_BIAS + (l & 1) * 512);
            const float bk = bias[vf];
            BSYNC(2, 384);                  // epi_X(l) done
            if (l < 5) aop_row(cX, bk);     // aop_X(l+1), overlaps MMA_Y(l)
            BSYNC(5, 384);                  // W(l) reads done (post MMA_Y k-loop)
            if (l < 5) {
                const unsigned char* sh = g_Wh[l + 1];
                const unsigned char* sl_ = g_Wl[l + 1];
                const uint32_t dh = sbase + (((l + 1) & 1) ? SM_WHI1 : SM_WHI0);
                for (int i = vf * 16; i < 34816; i += 2048) {
                    CPA16(dh + i, sh + i);
                    CPA16(sbase + SM_WLO + i, sl_ + i);
                }
                if (vf < 32)
                    CPA16(sbase + SM_BIAS + ((l + 1) & 1) * 512 + vf * 16,
                          (const unsigned char*)(blay + (l + 1) * 128) + vf * 16);
            } else {
                for (int i = vf * 16; i < 4352; i += 2048) {
                    CPA16(sbase + SM_WHI0 + i, g_WoH + i);
                    CPA16(sbase + SM_WLO + i, g_WoL + i);
                }
            }
            CPA_COMMIT();
            CPA_WAIT0();
            BARRIVE(1, 384);                // set X + W(l+1) ready
            BSYNC(4, 384);                  // epi_Y(l) done
            if (l < 5) aop_row(cY, bk);     // aop_Y(l+1), overlaps MMA_X(l+1)
            BARRIVE(3, 384);                // set Y ready
        }
    }

    __syncthreads();
    // ---- coalesced store ----
    {
        const float* stg = (const float*)(smem + SM_STAGE);
        const long long obase = (long long)blockIdx.x * 1458;
        for (int i = t; i < 1458; i += 384)
            out[obase + i] = stg[i];
    }
}

extern "C" void kernel_launch(void* const* d_in, const int* in_sizes, int n_in,
                              void* d_out, int out_size) {
    (void)in_sizes; (void)n_in; (void)out_size;
    prep_kernel<<<400, 256>>>((const float*)d_in[3], (const float*)d_in[5]);
    cudaFuncSetAttribute(gnn_mma, cudaFuncAttributeMaxDynamicSharedMemorySize, SMEM_BYTES);
    gnn_mma<<<4096, 384, SMEM_BYTES>>>(
        (const long long*)d_in[0],
        (const float*)d_in[1], (const float*)d_in[2],
        (const float*)d_in[4], (const float*)d_in[6],
        (float*)d_out);
}

// round 16
// speedup vs baseline: 1.0152x; 1.0152x over previous
#include <cuda_runtime.h>
#include <cuda_fp16.h>
#include <cstdint>

// Fused sudoku-GNN, split-fp16 HMMA, warp-specialized two-set pipeline.
// 384 threads: warps 0-7 = tensor group (T): MMA + epilogue; warps 8-11 =
// vector group (V): sudoku A-op + next-layer weight cp.async.
// Two independent sets (1 board each, M=96, own A buffer, row 400B).
// R16 = R12 + early Whi staging: Whi(l+1)+bias(l+1) cp.async is issued at the
// TOP of V's iteration (ping-ponged buffer is free), overlapping aop_X and
// T's MMAs; only the single-buffered Wlo(l+1) waits for id5 (post MMA_Y
// k-loop). Halves the weight-copy tail exposed on T's critical path.
// Barriers (identical to R12): id1 X+W ready (V->T), id2 X free (T->V),
// id3 Y ready, id4 Y free, id5 W free (T->V), id6 T-only epi guard.

#define ASTB 400         // A row bytes (25*16 -> conflict-free)
#define WSTB 272         // W row bytes (17*16)

#define SM_AX    0            // 128*400 = 51200
#define SM_AY    51200
#define SM_WHI0  102400       // 34816
#define SM_WHI1  137216
#define SM_WLO   172032
#define SM_BIAS  206848       // 2*512 ping/pong
#define SM_STAGE 207872       // Win staging (5120) / logits (5832)
#define SM_XS    213760       // 162 ints
#define SMEM_BYTES 214432

__device__ __align__(16) unsigned char g_Wh[6][34816];
__device__ __align__(16) unsigned char g_Wl[6][34816];
__device__ __align__(16) unsigned char g_WoH[4352];   // WoutT padded [16][136]
__device__ __align__(16) unsigned char g_WoL[4352];

__device__ __forceinline__ uint32_t smem_u32(const void* p) {
    uint32_t a;
    asm("{ .reg .u64 t; cvta.to.shared.u64 t, %1; cvt.u32.u64 %0, t; }" : "=r"(a) : "l"(p));
    return a;
}
#define CPA16(dst, src) asm volatile("cp.async.cg.shared.global [%0], [%1], 16;" :: "r"(dst), "l"(src))
#define CPA_COMMIT()    asm volatile("cp.async.commit_group;" ::: "memory")
#define CPA_WAIT0()     asm volatile("cp.async.wait_group 0;" ::: "memory")
#define BSYNC(id, cnt)  asm volatile("bar.sync %0, %1;" :: "r"(id), "r"(cnt) : "memory")
#define BARRIVE(id, cnt) asm volatile("bar.arrive %0, %1;" :: "r"(id), "r"(cnt) : "memory")

#define LDMX4(r, addr)                                                        \
    asm volatile("ldmatrix.sync.aligned.m8n8.x4.shared.b16 {%0,%1,%2,%3}, [%4];" \
        : "=r"((r)[0]), "=r"((r)[1]), "=r"((r)[2]), "=r"((r)[3]) : "r"(addr))
#define LDMX4T(r, addr)                                                       \
    asm volatile("ldmatrix.sync.aligned.m8n8.x4.trans.shared.b16 {%0,%1,%2,%3}, [%4];" \
        : "=r"((r)[0]), "=r"((r)[1]), "=r"((r)[2]), "=r"((r)[3]) : "r"(addr))
#define MMA16816(d, a, b)                                                     \
    asm volatile("mma.sync.aligned.m16n8k16.row.col.f32.f16.f16.f32 "         \
        "{%0,%1,%2,%3},{%4,%5,%6,%7},{%8,%9},{%0,%1,%2,%3};"                  \
        : "+f"((d)[0]), "+f"((d)[1]), "+f"((d)[2]), "+f"((d)[3])              \
        : "r"((a)[0]), "r"((a)[1]), "r"((a)[2]), "r"((a)[3]),                 \
          "r"((b)[0]), "r"((b)[1]))

// ---------- prep: split W to fp16 hi/lo [n][k] ----------
__global__ void prep_kernel(const float* __restrict__ Wlay,
                            const float* __restrict__ Wout) {
    int t = blockIdx.x * blockDim.x + threadIdx.x;
    if (t < 6 * 128 * 128) {
        int l = t >> 14, r = t & 16383, k = r >> 7, n = r & 127;
        float w = Wlay[t];
        __half hi = __float2half_rn(w);
        __half lo = __float2half_rn(w - __half2float(hi));
        uint32_t off = (uint32_t)n * WSTB + (uint32_t)k * 2;
        *(__half*)(g_Wh[l] + off) = hi;
        *(__half*)(g_Wl[l] + off) = lo;
    } else if (t < 6 * 128 * 128 + 16 * 128) {
        int r = t - 6 * 128 * 128;
        int j = r >> 7, k = r & 127;
        float w = (j < 9) ? Wout[k * 9 + j] : 0.f;
        __half hi = __float2half_rn(w);
        __half lo = __float2half_rn(w - __half2float(hi));
        uint32_t off = (uint32_t)j * WSTB + (uint32_t)k * 2;
        *(__half*)(g_WoH + off) = hi;
        *(__half*)(g_WoL + off) = lo;
    }
}

// ---------- A-op on one thread-private row: fp32 -> hi/lo in place ----------
__device__ __forceinline__ void aop_row(unsigned char* __restrict__ rowp) {
    const uint4* cp = (const uint4*)rowp;
    float Trow[9][3], Tcol[3][9];
#pragma unroll
    for (int i = 0; i < 9; i++) { Trow[i][0] = Trow[i][1] = Trow[i][2] = 0.f; }
#pragma unroll
    for (int j = 0; j < 9; j++) { Tcol[0][j] = Tcol[1][j] = Tcol[2][j] = 0.f; }
#pragma unroll
    for (int c = 0; c < 20; c++) {
        uint4 u = cp[c];
        float vv[4] = {__uint_as_float(u.x), __uint_as_float(u.y),
                       __uint_as_float(u.z), __uint_as_float(u.w)};
#pragma unroll
        for (int e = 0; e < 4; e++) {
            const int n = 4 * c + e, i = n / 9, j = n - 9 * i;
            Trow[i][j / 3] += vv[e];
            Tcol[i / 3][j] += vv[e];
        }
    }
    const float v80 = ((const float*)rowp)[80];
    Trow[8][2] += v80; Tcol[2][8] += v80;

    float RS[9], CS[9], BS[3][3];
#pragma unroll
    for (int i = 0; i < 9; i++) RS[i] = Trow[i][0] + Trow[i][1] + Trow[i][2];
#pragma unroll
    for (int j = 0; j < 9; j++) CS[j] = Tcol[0][j] + Tcol[1][j] + Tcol[2][j];
#pragma unroll
    for (int bi = 0; bi < 3; bi++)
#pragma unroll
        for (int bj = 0; bj < 3; bj++)
            BS[bi][bj] = Trow[3 * bi][bj] + Trow[3 * bi + 1][bj] + Trow[3 * bi + 2][bj];
    const float inv21 = 1.0f / 21.0f;
    float PR[9][3], CC[3][9];
#pragma unroll
    for (int i = 0; i < 9; i++)
#pragma unroll
        for (int jb = 0; jb < 3; jb++)
            PR[i][jb] = (RS[i] + BS[i / 3][jb] - Trow[i][jb]) * inv21;
#pragma unroll
    for (int ib = 0; ib < 3; ib++)
#pragma unroll
        for (int j = 0; j < 9; j++)
            CC[ib][j] = (CS[j] - Tcol[ib][j]) * inv21;

    unsigned char* hip = rowp;
    unsigned char* lop = rowp + 192;
#pragma unroll
    for (int c = 0; c < 10; c++) {
        uint32_t oh[4], ol[4];
#pragma unroll
        for (int e = 0; e < 4; e++) {
            const int n = 8 * c + 2 * e;
            const int i0 = n / 9, j0 = n - 9 * i0;
            const int n1 = n + 1, i1 = n1 / 9, j1 = n1 - 9 * i1;
            float g0 = PR[i0][j0 / 3] + CC[i0 / 3][j0];
            float g1 = PR[i1][j1 / 3] + CC[i1 / 3][j1];
            __half2 hh2 = __floats2half2_rn(g0, g1);
            float2 hf = __half22float2(hh2);
            __half2 ll2 = __floats2half2_rn(g0 - hf.x, g1 - hf.y);
            oh[e] = *(uint32_t*)&hh2;
            ol[e] = *(uint32_t*)&ll2;
        }
        *(uint4*)(hip + 16 * c) = make_uint4(oh[0], oh[1], oh[2], oh[3]);
        *(uint4*)(lop + 16 * c) = make_uint4(ol[0], ol[1], ol[2], ol[3]);
    }
    {
        float gg = PR[8][2] + CC[2][8];
        __half hh = __float2half_rn(gg);
        *(__half*)(hip + 160) = hh;
        *(__half*)(lop + 160) = __float2half_rn(gg - __half2float(hh));
    }
}

__global__ void __launch_bounds__(384)
gnn_mma(const long long* __restrict__ xraw,
        const float* __restrict__ Win,  const float* __restrict__ bin,
        const float* __restrict__ blay, const float* __restrict__ bout,
        float* __restrict__ out) {
    extern __shared__ unsigned char smem[];
    const int t = threadIdx.x, wid = t >> 5, lane = t & 31;
    const uint32_t sbase = smem_u32(smem);

    // ---- prologue: cp.async W(0) + bias(0) ----
    for (int i = t * 16; i < 34816; i += 384 * 16) {
        CPA16(sbase + SM_WHI0 + i, g_Wh[0] + i);
        CPA16(sbase + SM_WLO + i, g_Wl[0] + i);
    }
    if (t < 32) CPA16(sbase + SM_BIAS + t * 16, (const unsigned char*)blay + t * 16);
    CPA_COMMIT();

    // ---- x load (int64 vs int32 robust) + Win ----
    long long probe = (t < 162) ? xraw[t] : 0;
    const int is32 = __syncthreads_or(probe > 9 || probe < 0);
    {
        const long long gbase = (long long)blockIdx.x * 162;
        for (int i = t; i < 162; i += 384)
            ((int*)(smem + SM_XS))[i] =
                is32 ? ((const int*)xraw)[gbase + i] : (int)xraw[gbase + i];
    }
    for (int i = t; i < 1280; i += 384)
        ((float*)(smem + SM_STAGE))[i] = Win[i];
    __syncthreads();

    // ---- h0 = relu(Win[x]+bin) + aop(layer 0), thread-private rows ----
    if (t < 256) {
        const int f = t & 127, s = t >> 7;
        unsigned char* rowp = smem + (s ? SM_AY : SM_AX) + f * ASTB;
        const float bk = bin[f];
        const float* Wi = (const float*)(smem + SM_STAGE);
        const int* xr = (const int*)(smem + SM_XS) + s * 81;
#pragma unroll 5
        for (int c = 0; c < 20; c++) {
            float4 o;
            o.x = fmaxf(Wi[xr[4 * c + 0] * 128 + f] + bk, 0.f);
            o.y = fmaxf(Wi[xr[4 * c + 1] * 128 + f] + bk, 0.f);
            o.z = fmaxf(Wi[xr[4 * c + 2] * 128 + f] + bk, 0.f);
            o.w = fmaxf(Wi[xr[4 * c + 3] * 128 + f] + bk, 0.f);
            *(float4*)(rowp + 16 * c) = o;
        }
        ((float*)rowp)[80] = fmaxf(Wi[xr[80] * 128 + f] + bk, 0.f);
        aop_row(rowp);
    }
    CPA_WAIT0();
    __syncthreads();

    const uint32_t rowSel = (uint32_t)((lane & 7) + ((lane >> 4) << 3));
    const uint32_t aFrag  = rowSel * ASTB + ((lane >> 3) & 1) * 16;
    const uint32_t bPairOff = rowSel * WSTB + ((lane >> 3) & 1) * 16;

    if (wid < 8) {
        // ================= TENSOR GROUP =================
        const int mg = wid & 1, ng = wid >> 1;
        const int m0 = mg * 48, n0e = ng * 32;
        const uint32_t n0W = (uint32_t)n0e * WSTB;
#pragma unroll 1
        for (int l = 0; l <= 6; l++) {
            const uint32_t whiB = (l & 1) ? SM_WHI1 : SM_WHI0;
#pragma unroll 1
            for (int s2 = 0; s2 < 2; s2++) {
                BSYNC(s2 ? 3 : 1, 384);
                const uint32_t abase = s2 ? SM_AY : SM_AX;
                if (l < 6) {
                    float acc[3][4][4];
#pragma unroll
                    for (int ti = 0; ti < 3; ti++)
#pragma unroll
                        for (int tj = 0; tj < 4; tj++)
#pragma unroll
                            for (int e = 0; e < 4; e++) acc[ti][tj][e] = 0.f;
                    const uint32_t aHi = sbase + abase + aFrag + (uint32_t)m0 * 2;
                    const uint32_t aLo = aHi + 192;
                    const uint32_t bLo = sbase + SM_WLO + n0W + bPairOff;
                    const uint32_t bHi = sbase + whiB + n0W + bPairOff;
                    // ---- fused 3-term k-loop ----
#pragma unroll
                    for (int ks = 0; ks < 8; ks++) {
                        uint32_t bh[4][2], bl[4][2], r4[4];
                        LDMX4(r4, bHi + ks * 32);
                        bh[0][0] = r4[0]; bh[0][1] = r4[1]; bh[1][0] = r4[2]; bh[1][1] = r4[3];
                        LDMX4(r4, bHi + 16 * WSTB + ks * 32);
                        bh[2][0] = r4[0]; bh[2][1] = r4[1]; bh[3][0] = r4[2]; bh[3][1] = r4[3];
                        LDMX4(r4, bLo + ks * 32);
                        bl[0][0] = r4[0]; bl[0][1] = r4[1]; bl[1][0] = r4[2]; bl[1][1] = r4[3];
                        LDMX4(r4, bLo + 16 * WSTB + ks * 32);
                        bl[2][0] = r4[0]; bl[2][1] = r4[1]; bl[3][0] = r4[2]; bl[3][1] = r4[3];
#pragma unroll
                        for (int ti = 0; ti < 3; ti++) {
                            uint32_t ah[4], al[4];
                            LDMX4T(ah, aHi + ks * 6400 + ti * 32);
                            LDMX4T(al, aLo + ks * 6400 + ti * 32);
#pragma unroll
                            for (int tj = 0; tj < 4; tj++) MMA16816(acc[ti][tj], ah, bh[tj]);
#pragma unroll
                            for (int tj = 0; tj < 4; tj++) MMA16816(acc[ti][tj], ah, bl[tj]);
#pragma unroll
                            for (int tj = 0; tj < 4; tj++) MMA16816(acc[ti][tj], al, bh[tj]);
                        }
                    }
                    if (s2) BARRIVE(5, 384);          // W(l) reads done
                    BSYNC(6, 256);                    // T-only: A reads done before epi writes
                    const float* bias = (const float*)(smem + SM_BIAS + (l & 1) * 512);
                    if (l < 5) {
#pragma unroll
                        for (int ti = 0; ti < 3; ti++) {
                            const int rb = m0 + 16 * ti + (lane >> 2);
#pragma unroll
                            for (int tj = 0; tj < 4; tj++) {
                                const int c0 = n0e + 8 * tj + 2 * (lane & 3);
                                const float bb0 = bias[c0], bb1 = bias[c0 + 1];
#pragma unroll
                                for (int hh = 0; hh < 2; hh++) {
                                    const int r = rb + 8 * hh;
                                    if (r < 81) {
                                        *(float*)(smem + abase + (uint32_t)c0 * ASTB + r * 4) =
                                            fmaxf(acc[ti][tj][2 * hh] + bb0, 0.f);
                                        *(float*)(smem + abase + (uint32_t)(c0 + 1) * ASTB + r * 4) =
                                            fmaxf(acc[ti][tj][2 * hh + 1] + bb1, 0.f);
                                    }
                                }
                            }
                        }
                    } else {
                        // layer 5: split relu(acc+b) directly to hi/lo
#pragma unroll
                        for (int ti = 0; ti < 3; ti++) {
                            const int rb = m0 + 16 * ti + (lane >> 2);
#pragma unroll
                            for (int tj = 0; tj < 4; tj++) {
                                const int c0 = n0e + 8 * tj + 2 * (lane & 3);
                                const float bb0 = bias[c0], bb1 = bias[c0 + 1];
#pragma unroll
                                for (int hh = 0; hh < 2; hh++) {
                                    const int r = rb + 8 * hh;
                                    if (r < 81) {
                                        float v0 = fmaxf(acc[ti][tj][2 * hh] + bb0, 0.f);
                                        float v1 = fmaxf(acc[ti][tj][2 * hh + 1] + bb1, 0.f);
                                        __half h0h = __float2half_rn(v0);
                                        __half h1h = __float2half_rn(v1);
                                        const uint32_t o0 = (uint32_t)c0 * ASTB + r * 2;
                                        const uint32_t o1 = (uint32_t)(c0 + 1) * ASTB + r * 2;
                                        *(__half*)(smem + abase + o0) = h0h;
                                        *(__half*)(smem + abase + o1) = h1h;
                                        *(__half*)(smem + abase + 192 + o0) =
                                            __float2half_rn(v0 - __half2float(h0h));
                                        *(__half*)(smem + abase + 192 + o1) =
                                            __float2half_rn(v1 - __half2float(h1h));
                                    }
                                }
                            }
                        }
                    }
                    BARRIVE(s2 ? 4 : 2, 384);         // set free for V's next aop
                } else {
                    // ---- output layer: warps 0-5, 1 m16-tile x 16 n ----
                    if (wid < 6) {
                        float acc2[2][4];
#pragma unroll
                        for (int tj = 0; tj < 2; tj++)
#pragma unroll
                            for (int e = 0; e < 4; e++) acc2[tj][e] = 0.f;
                        const uint32_t aHi = sbase + abase + aFrag + (uint32_t)wid * 32;
                        const uint32_t aLo = aHi + 192;
                        const uint32_t bH = sbase + SM_WHI0 + bPairOff;
                        const uint32_t bL = sbase + SM_WLO + bPairOff;
#pragma unroll
                        for (int ks = 0; ks < 8; ks++) {
                            uint32_t b1[2][2], b2[2][2], r4[4];
                            LDMX4(r4, bH + ks * 32);
                            b1[0][0] = r4[0]; b1[0][1] = r4[1]; b1[1][0] = r4[2]; b1[1][1] = r4[3];
                            LDMX4(r4, bL + ks * 32);
                            b2[0][0] = r4[0]; b2[0][1] = r4[1]; b2[1][0] = r4[2]; b2[1][1] = r4[3];
                            uint32_t ah[4], al[4];
                            LDMX4T(ah, aHi + ks * 6400);
                            LDMX4T(al, aLo + ks * 6400);
#pragma unroll
                            for (int tj = 0; tj < 2; tj++) {
                                MMA16816(acc2[tj], ah, b1[tj]);
                                MMA16816(acc2[tj], ah, b2[tj]);
                                MMA16816(acc2[tj], al, b1[tj]);
                            }
                        }
                        float* stg = (float*)(smem + SM_STAGE);
#pragma unroll
                        for (int tj = 0; tj < 2; tj++) {
                            const int c0 = 8 * tj + 2 * (lane & 3);
#pragma unroll
                            for (int hh = 0; hh < 2; hh++) {
                                const int r = wid * 16 + (lane >> 2) + 8 * hh;
                                if (r < 81) {
                                    if (c0 < 9)
                                        stg[s2 * 729 + r * 9 + c0] = acc2[tj][2 * hh] + bout[c0];
                                    if (c0 + 1 < 9)
                                        stg[s2 * 729 + r * 9 + c0 + 1] = acc2[tj][2 * hh + 1] + bout[c0 + 1];
                                }
                            }
                        }
                    }
                }
            }
        }
    } else {
        // ================= VECTOR GROUP =================
        const int vf = t & 127;
        unsigned char* cX = smem + SM_AX + vf * ASTB;
        unsigned char* cY = smem + SM_AY + vf * ASTB;
        BARRIVE(1, 384);
        BARRIVE(3, 384);
#pragma unroll 1
        for (int l = 0; l < 6; l++) {
            BSYNC(2, 384);                  // epi_X(l) done
            // ---- EARLY: Whi(l+1)+bias(l+1) into free ping-pong buffer ----
            if (l < 5) {
                const uint32_t dh = sbase + (((l + 1) & 1) ? SM_WHI1 : SM_WHI0);
                const unsigned char* sh = g_Wh[l + 1];
                for (int i = vf * 16; i < 34816; i += 2048)
                    CPA16(dh + i, sh + i);
                if (vf < 32)
                    CPA16(sbase + SM_BIAS + ((l + 1) & 1) * 512 + vf * 16,
                          (const unsigned char*)(blay + (l + 1) * 128) + vf * 16);
            } else {
                // Wout hi half into WHI0 (free since MMA_Y(4))
                for (int i = vf * 16; i < 4352; i += 2048)
                    CPA16(sbase + SM_WHI0 + i, g_WoH + i);
            }
            CPA_COMMIT();
            if (l < 5) aop_row(cX);         // aop_X(l+1), overlaps MMA_Y(l)
            BSYNC(5, 384);                  // Wlo(l) reads done (post MMA_Y k-loop)
            if (l < 5) {
                const unsigned char* sl_ = g_Wl[l + 1];
                for (int i = vf * 16; i < 34816; i += 2048)
                    CPA16(sbase + SM_WLO + i, sl_ + i);
            } else {
                for (int i = vf * 16; i < 4352; i += 2048)
                    CPA16(sbase + SM_WLO + i, g_WoL + i);
            }
            CPA_COMMIT();
            CPA_WAIT0();
            BARRIVE(1, 384);                // set X + W(l+1) ready
            BSYNC(4, 384);                  // epi_Y(l) done
            if (l < 5) aop_row(cY);         // aop_Y(l+1), overlaps MMA_X(l+1)
            BARRIVE(3, 384);                // set Y ready
        }
    }

    __syncthreads();
    // ---- coalesced store ----
    {
        const float* stg = (const float*)(smem + SM_STAGE);
        const long long obase = (long long)blockIdx.x * 1458;
        for (int i = t; i < 1458; i += 384)
            out[obase + i] = stg[i];
    }
}

extern "C" void kernel_launch(void* const* d_in, const int* in_sizes, int n_in,
                              void* d_out, int out_size) {
    (void)in_sizes; (void)n_in; (void)out_size;
    prep_kernel<<<400, 256>>>((const float*)d_in[3], (const float*)d_in[5]);
    cudaFuncSetAttribute(gnn_mma, cudaFuncAttributeMaxDynamicSharedMemorySize, SMEM_BYTES);
    gnn_mma<<<4096, 384, SMEM_BYTES>>>(
        (const long long*)d_in[0],
        (const float*)d_in[1], (const float*)d_in[2],
        (const float*)d_in[4], (const float*)d_in[6],
        (float*)d_out);
}